// round 7
// baseline (speedup 1.0000x reference)
#include <cuda_runtime.h>
#include <math.h>

#define NS 100000
#define H 128
#define NBLK 592            // 4 blocks/SM * 148 SMs
#define NTHREADS 256
#define WPB 8
#define TROWS 43            // rows per tile (43*512B = 21.5KB per buffer)
// 100000 = 592*168 + 544
#define BASE_ROWS 168
#define EXTRA 544

// Per-block partials: 0:P+.mu 1:P-.mu 2:P+.sig 3:P-.sig 4:S+ 5:S-
__device__ float g_part[6][NBLK];
__device__ int g_count = 0;

__device__ __forceinline__ float d4(float4 a, float4 b) {
    return a.x * b.x + a.y * b.y + a.z * b.z + a.w * b.w;
}

// Swizzled 16B-unit index within a tile for logical (row, unit j in 0..31).
// Conflict-free for: quad-per-row reads (phase A), lane-per-unit reads (phase B),
// and row-per-warp stores (copy-in). Bijective within each row.
__device__ __forceinline__ int swz(int row, int j) {
    return row * 32 + (j & 24) + ((j & 7) ^ (j >> 3) ^ ((row & 1) << 2));
}

__device__ __forceinline__ void cp16(unsigned daddr, const void* gptr) {
    asm volatile("cp.async.cg.shared.global [%0], [%1], 16;" :: "r"(daddr), "l"(gptr));
}

__global__ __launch_bounds__(NTHREADS, 4) void fp_r7(
    const float* __restrict__ e, const float* __restrict__ q,
    const float* __restrict__ mu_w, const float* __restrict__ sigma_w,
    const float* __restrict__ w_key, const float* __restrict__ w_value,
    const float* __restrict__ mu_b, const float* __restrict__ sigma_b,
    float* __restrict__ out) {
    __shared__ float4 sbuf[2][TROWS * 32];   // 2 x 22016 B
    __shared__ float abuf[TROWS];
    __shared__ float wsum[WPB][6];
    __shared__ int is_last;

    const int tid = threadIdx.x;
    const int lane = tid & 31;
    const int warp = tid >> 5;
    const int b = blockIdx.x;
    const int cnt = BASE_ROWS + (b < EXTRA ? 1 : 0);
    const int start = b * BASE_ROWS + (b < EXTRA ? b : EXTRA);
    const int ntiles = (cnt + TROWS - 1) / TROWS;   // = 4

    // Phase-A role: quad (4 threads) per row; thread owns 32 columns.
    const int rowA = tid >> 2;
    const int qa = tid & 3;

    const float4* __restrict__ q4 = reinterpret_cast<const float4*>(q);
    float4 qv[8];
#pragma unroll
    for (int k = 0; k < 8; k++) qv[k] = q4[qa * 8 + k];
    float qn = 0.f;
#pragma unroll
    for (int k = 0; k < 8; k++) qn += d4(qv[k], qv[k]);
    qn += __shfl_xor_sync(0xffffffffu, qn, 1);
    qn += __shfl_xor_sync(0xffffffffu, qn, 2);   // quad covers all 128 cols
    const float rq = rsqrtf(qn);

    unsigned sb[2];
    sb[0] = (unsigned)__cvta_generic_to_shared(&sbuf[0][0]);
    sb[1] = (unsigned)__cvta_generic_to_shared(&sbuf[1][0]);

    // phase-B accumulators: lane owns columns lane*4 .. lane*4+3
    float pp0 = 0.f, pp1 = 0.f, pp2 = 0.f, pp3 = 0.f;
    float pm0 = 0.f, pm1 = 0.f, pm2 = 0.f, pm3 = 0.f;
    float sp = 0.f, sm = 0.f;

    // ---- issue copy of tile 0 ----
    {
        const int tcnt = (cnt < TROWS) ? cnt : TROWS;
        const char* src = (const char*)e + (size_t)start * 512;
        for (int idx = tid; idx < tcnt * 32; idx += NTHREADS) {
            int r = idx >> 5, j = idx & 31;
            cp16(sb[0] + swz(r, j) * 16, src + r * 512 + j * 16);
        }
        asm volatile("cp.async.commit_group;");
    }

    for (int t = 0; t < ntiles; t++) {
        const int bufi = t & 1;
        const int tcnt = (cnt - t * TROWS < TROWS) ? (cnt - t * TROWS) : TROWS;

        if (t + 1 < ntiles) {
            const int ncnt = (cnt - (t + 1) * TROWS < TROWS) ? (cnt - (t + 1) * TROWS) : TROWS;
            const char* src = (const char*)e + (size_t)(start + (t + 1) * TROWS) * 512;
            const unsigned dst = sb[bufi ^ 1];
            for (int idx = tid; idx < ncnt * 32; idx += NTHREADS) {
                int r = idx >> 5, j = idx & 31;
                cp16(dst + swz(r, j) * 16, src + r * 512 + j * 16);
            }
            asm volatile("cp.async.commit_group;");
            asm volatile("cp.async.wait_group 1;");
        } else {
            asm volatile("cp.async.wait_group 0;");
        }
        __syncthreads();   // tile t fully visible

        // ── Phase A: cosine per row (quad per row, 2-stage shuffle) ──
        {
            const int r = (rowA < tcnt) ? rowA : (tcnt - 1);
            const float4* rp = &sbuf[bufi][0];
            float d = 0.f, n = 0.f;
#pragma unroll
            for (int k = 0; k < 8; k++) {
                float4 a = rp[swz(r, qa * 8 + k)];
                d += d4(a, qv[k]);
                n += d4(a, a);
            }
            d += __shfl_xor_sync(0xffffffffu, d, 1);
            d += __shfl_xor_sync(0xffffffffu, d, 2);
            n += __shfl_xor_sync(0xffffffffu, n, 1);
            n += __shfl_xor_sync(0xffffffffu, n, 2);
            float c = d * rsqrtf(n) * rq;
            if (qa == 0 && rowA < tcnt) abuf[rowA] = c;
        }
        __syncthreads();   // abuf ready

        // ── Phase B: accumulate P+/P- (no shuffles, smem-hot) ──
        for (int r = warp; r < tcnt; r += WPB) {
            float4 v = sbuf[bufi][swz(r, lane)];
            float c = abuf[r];
            float ap = fmaxf(c, 0.f), am = fmaxf(-c, 0.f);
            sp += ap;  sm += am;
            pp0 += ap * v.x;  pm0 += am * v.x;
            pp1 += ap * v.y;  pm1 += am * v.y;
            pp2 += ap * v.z;  pm2 += am * v.z;
            pp3 += ap * v.w;  pm3 += am * v.w;
        }
        __syncthreads();   // buffer/abuf free for reuse
    }

    // ── Epilogue: pre-dot lane's columns with mu_w / sigma_w ──
    float4 mw = reinterpret_cast<const float4*>(mu_w)[lane];
    float4 sw = reinterpret_cast<const float4*>(sigma_w)[lane];
    float t0 = pp0 * mw.x + pp1 * mw.y + pp2 * mw.z + pp3 * mw.w;
    float t1 = pm0 * mw.x + pm1 * mw.y + pm2 * mw.z + pm3 * mw.w;
    float t2 = pp0 * sw.x + pp1 * sw.y + pp2 * sw.z + pp3 * sw.w;
    float t3 = pm0 * sw.x + pm1 * sw.y + pm2 * sw.z + pm3 * sw.w;
#pragma unroll
    for (int o = 16; o > 0; o >>= 1) {
        t0 += __shfl_xor_sync(0xffffffffu, t0, o);
        t1 += __shfl_xor_sync(0xffffffffu, t1, o);
        t2 += __shfl_xor_sync(0xffffffffu, t2, o);
        t3 += __shfl_xor_sync(0xffffffffu, t3, o);
        sp += __shfl_xor_sync(0xffffffffu, sp, o);
        sm += __shfl_xor_sync(0xffffffffu, sm, o);
    }
    if (lane == 0) {
        wsum[warp][0] = t0;
        wsum[warp][1] = t1;
        wsum[warp][2] = t2;
        wsum[warp][3] = t3;
        wsum[warp][4] = sp * 0.03125f;   // all 32 lanes held each row's a
        wsum[warp][5] = sm * 0.03125f;
    }
    __syncthreads();
    if (tid < 6) {
        float s = 0.f;
#pragma unroll
        for (int w = 0; w < WPB; w++) s += wsum[w][tid];
        g_part[tid][b] = s;
    }
    __threadfence();
    __syncthreads();
    if (tid == 0)
        is_last = (atomicAdd(&g_count, 1) == NBLK - 1) ? 1 : 0;
    __syncthreads();
    if (!is_last) return;

    // ── Last block: final 6-scalar reduce + the 8 outputs ──
    __shared__ float tot[6];
    if (warp < 6) {
        float s = 0.f;
#pragma unroll
        for (int i = 0; i < (NBLK + 31) / 32; i++) {
            int j = lane + i * 32;
            if (j < NBLK) s += __ldcg(&g_part[warp][j]);
        }
#pragma unroll
        for (int o = 16; o > 0; o >>= 1) s += __shfl_xor_sync(0xffffffffu, s, o);
        if (lane == 0) tot[warp] = s;
    }
    __syncthreads();
    if (tid < 4) {
        const float Sp = fmaxf(tot[4], 1e-6f);
        const float Sm = fmaxf(tot[5], 1e-6f);
        float wk = w_key[tid];
        float wv = w_value[tid];
        bool pos = (wk > 0.f);
        float dmu = pos ? (tot[0] / Sp) : (tot[1] / Sm);
        float dsg = pos ? (tot[2] / Sp) : (tot[3] / Sm);
        float mu_z = wv * dmu + mu_b[0];
        float x = wv * dsg + sigma_b[0];
        float sig_z = fmaxf(x, 0.f) + log1pf(expf(-fabsf(x)));
        out[tid] = mu_z;
        out[4 + tid] = sig_z;
    }
    if (tid == 0) g_count = 0;   // reset for next graph replay
}

extern "C" void kernel_launch(void* const* d_in, const int* in_sizes, int n_in,
                              void* d_out, int out_size) {
    const float* e       = (const float*)d_in[0];
    const float* w_key   = (const float*)d_in[1];
    const float* w_value = (const float*)d_in[2];
    const float* q       = (const float*)d_in[3];
    const float* mu_w    = (const float*)d_in[4];
    const float* mu_b    = (const float*)d_in[5];
    const float* sigma_w = (const float*)d_in[6];
    const float* sigma_b = (const float*)d_in[7];
    float* out = (float*)d_out;

    fp_r7<<<NBLK, NTHREADS>>>(e, q, mu_w, sigma_w, w_key, w_value, mu_b, sigma_b, out);
}

// round 8
// speedup vs baseline: 1.2437x; 1.2437x over previous
#include <cuda_runtime.h>
#include <math.h>

#define NS 100000
#define NPAIR (NS / 2)
#define H 128
#define NBLK 444            // 3 blocks/SM * 148 SMs: one balanced wave at occ=3
#define NTHREADS 256
#define WPB (NTHREADS / 32)
#define TOTW (NBLK * WPB)   // 3552 warps

// Per-block partials: 0:P+.mu 1:P-.mu 2:P+.sig 3:P-.sig 4:S+ 5:S-
__device__ float g_part[6][NBLK];
__device__ int g_count = 0;

__device__ __forceinline__ float dot8(float4 a, float4 b, float4 x, float4 y) {
    return a.x * x.x + a.y * x.y + a.z * x.z + a.w * x.w +
           b.x * y.x + b.y * y.y + b.z * y.z + b.w * y.w;
}

__global__ __launch_bounds__(NTHREADS, 3) void fp_r8(
    const float* __restrict__ e, const float* __restrict__ q,
    const float* __restrict__ mu_w, const float* __restrict__ sigma_w,
    const float* __restrict__ w_key, const float* __restrict__ w_value,
    const float* __restrict__ mu_b, const float* __restrict__ sigma_b,
    float* __restrict__ out) {
    const int lane = threadIdx.x & 31;
    const int warp = threadIdx.x >> 5;
    const int sub  = lane & 15;   // lane within 16-lane row group
    const int half = lane >> 4;   // which row of the pair
    const int gw = blockIdx.x * WPB + warp;

    const float4* __restrict__ e4 = reinterpret_cast<const float4*>(e);
    const float4* __restrict__ q4 = reinterpret_cast<const float4*>(q);

    float4 q0 = q4[sub * 2 + 0];
    float4 q1 = q4[sub * 2 + 1];
    float qn = dot8(q0, q1, q0, q1);
#pragma unroll
    for (int o = 8; o > 0; o >>= 1) qn += __shfl_xor_sync(0xffffffffu, qn, o);
    const float rq = rsqrtf(qn);

    float pp[8] = {0, 0, 0, 0, 0, 0, 0, 0};
    float pm[8] = {0, 0, 0, 0, 0, 0, 0, 0};
    float sp = 0.f, sm = 0.f;

    // ── software-pipelined main loop: 2 pairs per iteration, prefetch next 2 ──
    int p = gw;                             // gw < 3552 < NPAIR: A0 always valid
    bool v1 = (p + TOTW) < NPAIR;
    float4 A00, A01, A10, A11;
    {
        int ia = (2 * p + half) * 32 + sub * 2;
        A00 = e4[ia]; A01 = e4[ia + 1];
        int p1 = v1 ? (p + TOTW) : 0;
        int ib = (2 * p1 + half) * 32 + sub * 2;
        A10 = e4[ib]; A11 = e4[ib + 1];
    }
    for (; p < NPAIR; p += 2 * TOTW) {
        // prefetch next two pairs (clamped to pair 0 when OOB; masked below)
        int np0 = p + 2 * TOTW;
        int np1 = p + 3 * TOTW;
        bool nv1 = np1 < NPAIR;
        int cp0 = (np0 < NPAIR) ? np0 : 0;
        int cp1 = nv1 ? np1 : 0;
        int ia = (2 * cp0 + half) * 32 + sub * 2;
        float4 B00 = e4[ia], B01 = e4[ia + 1];
        int ib = (2 * cp1 + half) * 32 + sub * 2;
        float4 B10 = e4[ib], B11 = e4[ib + 1];

        // compute on current A pairs (loads above stay in flight through this)
        float d0 = dot8(A00, A01, q0, q1);
        float n0 = dot8(A00, A01, A00, A01);
        float d1 = dot8(A10, A11, q0, q1);
        float n1 = dot8(A10, A11, A10, A11);
#pragma unroll
        for (int o = 8; o > 0; o >>= 1) {
            d0 += __shfl_xor_sync(0xffffffffu, d0, o);
            n0 += __shfl_xor_sync(0xffffffffu, n0, o);
            d1 += __shfl_xor_sync(0xffffffffu, d1, o);
            n1 += __shfl_xor_sync(0xffffffffu, n1, o);
        }
        float r0 = rsqrtf(n0) * rq;
        float r1 = rsqrtf(n1) * rq;
        float ap0 = fmaxf(d0, 0.f) * r0, am0 = fmaxf(-d0, 0.f) * r0;
        float ap1 = v1 ? fmaxf(d1, 0.f) * r1 : 0.f;
        float am1 = v1 ? fmaxf(-d1, 0.f) * r1 : 0.f;
        sp += ap0 + ap1;
        sm += am0 + am1;
        pp[0] += ap0 * A00.x + ap1 * A10.x;  pm[0] += am0 * A00.x + am1 * A10.x;
        pp[1] += ap0 * A00.y + ap1 * A10.y;  pm[1] += am0 * A00.y + am1 * A10.y;
        pp[2] += ap0 * A00.z + ap1 * A10.z;  pm[2] += am0 * A00.z + am1 * A10.z;
        pp[3] += ap0 * A00.w + ap1 * A10.w;  pm[3] += am0 * A00.w + am1 * A10.w;
        pp[4] += ap0 * A01.x + ap1 * A11.x;  pm[4] += am0 * A01.x + am1 * A11.x;
        pp[5] += ap0 * A01.y + ap1 * A11.y;  pm[5] += am0 * A01.y + am1 * A11.y;
        pp[6] += ap0 * A01.z + ap1 * A11.z;  pm[6] += am0 * A01.z + am1 * A11.z;
        pp[7] += ap0 * A01.w + ap1 * A11.w;  pm[7] += am0 * A01.w + am1 * A11.w;

        A00 = B00; A01 = B01; A10 = B10; A11 = B11;
        v1 = nv1;
    }

    // ── Warp epilogue: combine halves, pre-dot with mu_w/sigma_w ──
#pragma unroll
    for (int i = 0; i < 8; i++) {
        pp[i] += __shfl_xor_sync(0xffffffffu, pp[i], 16);
        pm[i] += __shfl_xor_sync(0xffffffffu, pm[i], 16);
    }
    const float4* __restrict__ mw4 = reinterpret_cast<const float4*>(mu_w);
    const float4* __restrict__ sw4 = reinterpret_cast<const float4*>(sigma_w);
    float4 m0 = mw4[sub * 2], m1 = mw4[sub * 2 + 1];
    float4 s0 = sw4[sub * 2], s1 = sw4[sub * 2 + 1];
    float mwv[8] = {m0.x, m0.y, m0.z, m0.w, m1.x, m1.y, m1.z, m1.w};
    float swv[8] = {s0.x, s0.y, s0.z, s0.w, s1.x, s1.y, s1.z, s1.w};
    float t0 = 0, t1 = 0, t2 = 0, t3 = 0;
#pragma unroll
    for (int i = 0; i < 8; i++) {
        t0 += pp[i] * mwv[i];
        t1 += pm[i] * mwv[i];
        t2 += pp[i] * swv[i];
        t3 += pm[i] * swv[i];
    }
#pragma unroll
    for (int o = 8; o > 0; o >>= 1) {
        t0 += __shfl_xor_sync(0xffffffffu, t0, o);
        t1 += __shfl_xor_sync(0xffffffffu, t1, o);
        t2 += __shfl_xor_sync(0xffffffffu, t2, o);
        t3 += __shfl_xor_sync(0xffffffffu, t3, o);
    }
    // sp/sm held once per lane of each row's 16-group -> scale 1/16
#pragma unroll
    for (int o = 16; o > 0; o >>= 1) {
        sp += __shfl_xor_sync(0xffffffffu, sp, o);
        sm += __shfl_xor_sync(0xffffffffu, sm, o);
    }

    __shared__ float wsum[WPB][6];
    __shared__ int is_last;
    if (lane == 0) {
        wsum[warp][0] = t0;
        wsum[warp][1] = t1;
        wsum[warp][2] = t2;
        wsum[warp][3] = t3;
        wsum[warp][4] = sp * 0.0625f;
        wsum[warp][5] = sm * 0.0625f;
    }
    __syncthreads();
    if (threadIdx.x < 6) {
        float s = 0.f;
#pragma unroll
        for (int w = 0; w < WPB; w++) s += wsum[w][threadIdx.x];
        g_part[threadIdx.x][blockIdx.x] = s;
    }
    __threadfence();
    __syncthreads();
    if (threadIdx.x == 0)
        is_last = (atomicAdd(&g_count, 1) == NBLK - 1) ? 1 : 0;
    __syncthreads();
    if (!is_last) return;

    // ── Last block: final 6-scalar reduce + the 8 outputs ──
    __shared__ float tot[6];
    if (warp < 6) {
        float s = 0.f;
#pragma unroll
        for (int i = 0; i < (NBLK + 31) / 32; i++) {
            int j = lane + i * 32;
            if (j < NBLK) s += __ldcg(&g_part[warp][j]);
        }
#pragma unroll
        for (int o = 16; o > 0; o >>= 1) s += __shfl_xor_sync(0xffffffffu, s, o);
        if (lane == 0) tot[warp] = s;
    }
    __syncthreads();
    if (threadIdx.x < 4) {
        const int t = threadIdx.x;
        const float Sp = fmaxf(tot[4], 1e-6f);
        const float Sm = fmaxf(tot[5], 1e-6f);
        float wk = w_key[t];
        float wv = w_value[t];
        bool pos = (wk > 0.f);
        float dmu = pos ? (tot[0] / Sp) : (tot[1] / Sm);
        float dsg = pos ? (tot[2] / Sp) : (tot[3] / Sm);
        float mu_z = wv * dmu + mu_b[0];
        float x = wv * dsg + sigma_b[0];
        float sig_z = fmaxf(x, 0.f) + log1pf(expf(-fabsf(x)));
        out[t] = mu_z;
        out[4 + t] = sig_z;
    }
    if (threadIdx.x == 0) g_count = 0;  // reset for next graph replay
}

extern "C" void kernel_launch(void* const* d_in, const int* in_sizes, int n_in,
                              void* d_out, int out_size) {
    const float* e       = (const float*)d_in[0];
    const float* w_key   = (const float*)d_in[1];
    const float* w_value = (const float*)d_in[2];
    const float* q       = (const float*)d_in[3];
    const float* mu_w    = (const float*)d_in[4];
    const float* mu_b    = (const float*)d_in[5];
    const float* sigma_w = (const float*)d_in[6];
    const float* sigma_b = (const float*)d_in[7];
    float* out = (float*)d_out;

    fp_r8<<<NBLK, NTHREADS>>>(e, q, mu_w, sigma_w, w_key, w_value, mu_b, sigma_b, out);
}

// round 9
// speedup vs baseline: 1.2786x; 1.0281x over previous
#include <cuda_runtime.h>
#include <math.h>

#define NS 100000
#define NPAIR (NS / 2)
#define H 128
#define NBLK 740            // 5 blocks/SM * 148 SMs: one balanced wave at occ=5
#define NTHREADS 256
#define WPB (NTHREADS / 32)
#define TOTW (NBLK * WPB)   // 5920 warps

// Per-block partials: 0:P+.mu 1:P-.mu 2:P+.sig 3:P-.sig 4:S+ 5:S-
__device__ float g_part[6][NBLK];
__device__ int g_count = 0;

__device__ __forceinline__ float dot8(float4 a, float4 b, float4 x, float4 y) {
    return a.x * x.x + a.y * x.y + a.z * x.z + a.w * x.w +
           b.x * y.x + b.y * y.y + b.z * y.z + b.w * y.w;
}

__global__ __launch_bounds__(NTHREADS, 5) void fp_r9(
    const float* __restrict__ e, const float* __restrict__ q,
    const float* __restrict__ mu_w, const float* __restrict__ sigma_w,
    const float* __restrict__ w_key, const float* __restrict__ w_value,
    const float* __restrict__ mu_b, const float* __restrict__ sigma_b,
    float* __restrict__ out) {
    const int lane = threadIdx.x & 31;
    const int warp = threadIdx.x >> 5;
    const int sub  = lane & 15;   // lane within 16-lane row group
    const int half = lane >> 4;   // which row of the pair
    const int gw = blockIdx.x * WPB + warp;

    const float4* __restrict__ e4 = reinterpret_cast<const float4*>(e);
    const float4* __restrict__ q4 = reinterpret_cast<const float4*>(q);

    // q fragment, pre-scaled by 1/||q|| so c = d * rsqrt(n)
    float4 q0 = q4[sub * 2 + 0];
    float4 q1 = q4[sub * 2 + 1];
    float qn = dot8(q0, q1, q0, q1);
#pragma unroll
    for (int o = 8; o > 0; o >>= 1) qn += __shfl_xor_sync(0xffffffffu, qn, o);
    const float rq = rsqrtf(qn);
    q0.x *= rq; q0.y *= rq; q0.z *= rq; q0.w *= rq;
    q1.x *= rq; q1.y *= rq; q1.z *= rq; q1.w *= rq;

    float pp[8] = {0, 0, 0, 0, 0, 0, 0, 0};
    float pm[8] = {0, 0, 0, 0, 0, 0, 0, 0};
    float sp = 0.f, sm = 0.f;

    // lean main loop: one row-pair per iteration, pointer-strided (32-bit offsets)
    const float4* base = e4 + ((2 * gw + half) * 32 + sub * 2);
    for (int p = gw; p < NPAIR; p += TOTW, base += TOTW * 64) {
        float4 a0 = base[0];
        float4 a1 = base[1];
        float d = dot8(a0, a1, q0, q1);
        float n = dot8(a0, a1, a0, a1);
#pragma unroll
        for (int o = 8; o > 0; o >>= 1) {
            d += __shfl_xor_sync(0xffffffffu, d, o);
            n += __shfl_xor_sync(0xffffffffu, n, o);
        }
        float r = rsqrtf(n);
        float ap = fmaxf(d, 0.f) * r;
        float am = fmaxf(-d, 0.f) * r;
        sp += ap;
        sm += am;
        pp[0] += ap * a0.x;  pm[0] += am * a0.x;
        pp[1] += ap * a0.y;  pm[1] += am * a0.y;
        pp[2] += ap * a0.z;  pm[2] += am * a0.z;
        pp[3] += ap * a0.w;  pm[3] += am * a0.w;
        pp[4] += ap * a1.x;  pm[4] += am * a1.x;
        pp[5] += ap * a1.y;  pm[5] += am * a1.y;
        pp[6] += ap * a1.z;  pm[6] += am * a1.z;
        pp[7] += ap * a1.w;  pm[7] += am * a1.w;
    }

    // ── Warp epilogue: combine halves, pre-dot with mu_w/sigma_w ──
#pragma unroll
    for (int i = 0; i < 8; i++) {
        pp[i] += __shfl_xor_sync(0xffffffffu, pp[i], 16);
        pm[i] += __shfl_xor_sync(0xffffffffu, pm[i], 16);
    }
    const float4* __restrict__ mw4 = reinterpret_cast<const float4*>(mu_w);
    const float4* __restrict__ sw4 = reinterpret_cast<const float4*>(sigma_w);
    float4 m0 = mw4[sub * 2], m1 = mw4[sub * 2 + 1];
    float4 s0 = sw4[sub * 2], s1 = sw4[sub * 2 + 1];
    float mwv[8] = {m0.x, m0.y, m0.z, m0.w, m1.x, m1.y, m1.z, m1.w};
    float swv[8] = {s0.x, s0.y, s0.z, s0.w, s1.x, s1.y, s1.z, s1.w};
    float t0 = 0, t1 = 0, t2 = 0, t3 = 0;
#pragma unroll
    for (int i = 0; i < 8; i++) {
        t0 += pp[i] * mwv[i];
        t1 += pm[i] * mwv[i];
        t2 += pp[i] * swv[i];
        t3 += pm[i] * swv[i];
    }
#pragma unroll
    for (int o = 8; o > 0; o >>= 1) {
        t0 += __shfl_xor_sync(0xffffffffu, t0, o);
        t1 += __shfl_xor_sync(0xffffffffu, t1, o);
        t2 += __shfl_xor_sync(0xffffffffu, t2, o);
        t3 += __shfl_xor_sync(0xffffffffu, t3, o);
    }
    // sp/sm held once per lane of each row's 16-group -> scale 1/16
#pragma unroll
    for (int o = 16; o > 0; o >>= 1) {
        sp += __shfl_xor_sync(0xffffffffu, sp, o);
        sm += __shfl_xor_sync(0xffffffffu, sm, o);
    }

    __shared__ float wsum[WPB][6];
    __shared__ int is_last;
    if (lane == 0) {
        wsum[warp][0] = t0;
        wsum[warp][1] = t1;
        wsum[warp][2] = t2;
        wsum[warp][3] = t3;
        wsum[warp][4] = sp * 0.0625f;
        wsum[warp][5] = sm * 0.0625f;
    }
    __syncthreads();
    if (threadIdx.x < 6) {
        float s = 0.f;
#pragma unroll
        for (int w = 0; w < WPB; w++) s += wsum[w][threadIdx.x];
        g_part[threadIdx.x][blockIdx.x] = s;
    }
    __threadfence();
    __syncthreads();
    if (threadIdx.x == 0)
        is_last = (atomicAdd(&g_count, 1) == NBLK - 1) ? 1 : 0;
    __syncthreads();
    if (!is_last) return;

    // ── Last block: final 6-scalar reduce + the 8 outputs ──
    __shared__ float tot[6];
    if (warp < 6) {
        float s = 0.f;
#pragma unroll
        for (int i = 0; i < (NBLK + 31) / 32; i++) {
            int j = lane + i * 32;
            if (j < NBLK) s += __ldcg(&g_part[warp][j]);
        }
#pragma unroll
        for (int o = 16; o > 0; o >>= 1) s += __shfl_xor_sync(0xffffffffu, s, o);
        if (lane == 0) tot[warp] = s;
    }
    __syncthreads();
    if (threadIdx.x < 4) {
        const int t = threadIdx.x;
        const float Sp = fmaxf(tot[4], 1e-6f);
        const float Sm = fmaxf(tot[5], 1e-6f);
        float wk = w_key[t];
        float wv = w_value[t];
        bool pos = (wk > 0.f);
        float dmu = pos ? (tot[0] / Sp) : (tot[1] / Sm);
        float dsg = pos ? (tot[2] / Sp) : (tot[3] / Sm);
        float mu_z = wv * dmu + mu_b[0];
        float x = wv * dsg + sigma_b[0];
        float sig_z = fmaxf(x, 0.f) + log1pf(expf(-fabsf(x)));
        out[t] = mu_z;
        out[4 + t] = sig_z;
    }
    if (threadIdx.x == 0) g_count = 0;  // reset for next graph replay
}

extern "C" void kernel_launch(void* const* d_in, const int* in_sizes, int n_in,
                              void* d_out, int out_size) {
    const float* e       = (const float*)d_in[0];
    const float* w_key   = (const float*)d_in[1];
    const float* w_value = (const float*)d_in[2];
    const float* q       = (const float*)d_in[3];
    const float* mu_w    = (const float*)d_in[4];
    const float* mu_b    = (const float*)d_in[5];
    const float* sigma_w = (const float*)d_in[6];
    const float* sigma_b = (const float*)d_in[7];
    float* out = (float*)d_out;

    fp_r9<<<NBLK, NTHREADS>>>(e, q, mu_w, sigma_w, w_key, w_value, mu_b, sigma_b, out);
}